// round 11
// baseline (speedup 1.0000x reference)
#include <cuda_runtime.h>
#include <cuda_bf16.h>
#include <cstdint>

// Problem dims (fixed by the dataset)
#define BB 8
#define NSEQ 2048
#define DD 1024
#define DKK 64
#define MTOT (BB*NSEQ)   // 16384

// ---------------- scratch (static __device__ — no allocation) ----------------
__device__ float    g_QKFP[(long)MTOT*256];  // Q[0:64] K[64:128] F[128:192] P[192:256]
__device__ float    g_U2part[32*DKK*DD];     // split-K partials of U2
__device__ float    g_Tpart[32*BB*DKK*DKK];  // split-L partials of T
__device__ uint32_t g_Wh[256*512];           // Wext bf16-hi, packed k-pairs
__device__ uint32_t g_Wl[64*512];            // Wext bf16-lo, rows 128..191 (W1)
__device__ uint32_t g_fcH[(long)MTOT*32];    // fc bf16-hi packed
__device__ uint32_t g_fcL[(long)MTOT*32];    // fc bf16-lo packed
__device__ uint32_t g_W2h[1024*32];          // W2 bf16-hi packed
__device__ uint32_t g_W2l[1024*32];          // W2 bf16-lo packed

// ---------------------------------------------------------------------------
// helpers
// ---------------------------------------------------------------------------
__device__ __forceinline__ float tf32_rna(float x) {
    uint32_t r;
    asm("cvt.rna.tf32.f32 %0, %1;" : "=r"(r) : "f"(x));
    return __uint_as_float(r);
}
__device__ __forceinline__ uint32_t f2u(float f) { return __float_as_uint(f); }
__device__ __forceinline__ uint32_t b2u(__nv_bfloat162 v) {
    return *reinterpret_cast<uint32_t*>(&v);
}
__device__ __forceinline__ void cvt_hilo(float x, float y,
                                         __nv_bfloat162& h, __nv_bfloat162& l)
{
    h = __floats2bfloat162_rn(x, y);
    l = __floats2bfloat162_rn(x - __bfloat162float(h.x), y - __bfloat162float(h.y));
}

__device__ __forceinline__ void mma_tf32(float (&d)[4],
    uint32_t a0, uint32_t a1, uint32_t a2, uint32_t a3,
    uint32_t b0, uint32_t b1)
{
    asm volatile(
        "mma.sync.aligned.m16n8k8.row.col.f32.tf32.tf32.f32 "
        "{%0,%1,%2,%3},{%4,%5,%6,%7},{%8,%9},{%0,%1,%2,%3};"
        : "+f"(d[0]), "+f"(d[1]), "+f"(d[2]), "+f"(d[3])
        : "r"(a0), "r"(a1), "r"(a2), "r"(a3), "r"(b0), "r"(b1));
}

__device__ __forceinline__ void mma_bf16(float (&d)[4],
    const uint32_t (&a)[4], const uint32_t (&b)[2])
{
    asm volatile(
        "mma.sync.aligned.m16n8k16.row.col.f32.bf16.bf16.f32 "
        "{%0,%1,%2,%3},{%4,%5,%6,%7},{%8,%9},{%0,%1,%2,%3};"
        : "+f"(d[0]), "+f"(d[1]), "+f"(d[2]), "+f"(d[3])
        : "r"(a[0]), "r"(a[1]), "r"(a[2]), "r"(a[3]), "r"(b[0]), "r"(b[1]));
}

__device__ __forceinline__ void ldmx4(uint32_t (&r)[4], uint32_t addr) {
    asm volatile("ldmatrix.sync.aligned.m8n8.x4.shared.b16 {%0,%1,%2,%3}, [%4];"
        : "=r"(r[0]), "=r"(r[1]), "=r"(r[2]), "=r"(r[3]) : "r"(addr));
}
__device__ __forceinline__ void ldmx2(uint32_t (&r)[2], uint32_t addr) {
    asm volatile("ldmatrix.sync.aligned.m8n8.x2.shared.b16 {%0,%1}, [%2];"
        : "=r"(r[0]), "=r"(r[1]) : "r"(addr));
}

__device__ __forceinline__ void cp16(uint32_t smem_addr, const void* gptr) {
    asm volatile("cp.async.cg.shared.global [%0], [%1], 16;"
        :: "r"(smem_addr), "l"(gptr));
}
__device__ __forceinline__ void cp_commit() {
    asm volatile("cp.async.commit_group;" ::: "memory");
}
__device__ __forceinline__ void cp_wait0() {
    asm volatile("cp.async.wait_group 0;" ::: "memory");
}

// ===========================================================================
// prep_w: builds bf16 weight planes directly from the inputs.
// Wh rows: 0..63 Wq, 64..127 Wk, 128..191 W1 (lo plane -> Wl), 192..255 U2
// (U2 summed inline from the 32 split-K partials — same order as reduceN).
// Also converts W2 -> W2h/W2l.
// ===========================================================================
__global__ void prep_w(const float* __restrict__ Wq, const float* __restrict__ Wk,
                       const float* __restrict__ W1, const float* __restrict__ u2p,
                       const float* __restrict__ W2,
                       uint32_t* __restrict__ Wh, uint32_t* __restrict__ Wl,
                       uint32_t* __restrict__ W2h, uint32_t* __restrict__ W2l)
{
    int i = blockIdx.x * 256 + threadIdx.x;
    if (i < 256*512) {
        int row = i >> 9, p = i & 511;
        float x, y;
        if (row < 128) {
            const float* W = (row < 64) ? Wq : Wk;
            int r = row & 63;
            x = W[r*DD + 2*p];  y = W[r*DD + 2*p + 1];
        } else if (row < 192) {
            int r = row - 128;
            x = W1[r*DD + 2*p];  y = W1[r*DD + 2*p + 1];
        } else {
            int r = row - 192;
            float sx = 0.f, sy = 0.f;
            for (int s = 0; s < 32; s++) {
                sx += u2p[(long)s*DKK*DD + r*DD + 2*p];
                sy += u2p[(long)s*DKK*DD + r*DD + 2*p + 1];
            }
            x = sx;  y = sy;
        }
        __nv_bfloat162 h, l;
        cvt_hilo(x, y, h, l);
        Wh[i] = b2u(h);
        if (row >= 128 && row < 192) Wl[(row - 128) * 512 + p] = b2u(l);
    } else {
        int j = i - 256*512;
        if (j < 1024*32) {
            __nv_bfloat162 h, l;
            cvt_hilo(W2[2*j], W2[2*j + 1], h, l);
            W2h[j] = b2u(h);
            W2l[j] = b2u(l);
        }
    }
}

// ===========================================================================
// qkfp_fused: C[M,256] = x[M,1024] * Wext[256,1024]^T, ONE pass over x.
// F n-tile (j==2) gets the 3-product hi/lo split. BM=64, BN=256, BK=32,
// 256 threads (8 warps on n), 2 blocks/SM, grid=256 = one wave on 148 SMs.
// 2-stage double-buffered dynamic smem (70KB), ONE __syncthreads per iter.
// MMA ordering: all-fragments load -> 16 independent hh MMAs -> F lo pass.
// Per-accumulator order (hh, hl, lh per kp) matches prior rounds exactly.
// Stage layout (uint32): Ah[0,1280) Al[1280,2560) Bh[2560,7680) Bl[7680,8960)
// ===========================================================================
extern __shared__ uint32_t smem_dyn[];

__global__ void __launch_bounds__(256, 2)
qkfp_fused(const float* __restrict__ xg, const uint32_t* __restrict__ Wh,
           const uint32_t* __restrict__ Wl, float* __restrict__ Cg)
{
    constexpr int SP = 20;            // uint32 per smem row (80B) — conflict-free
    constexpr int OA_L = 1280;
    constexpr int OB_H = 2560;
    constexpr int OB_L = 7680;
    constexpr int STG  = 8960;        // stage stride in uint32
    constexpr uint32_t STGB = STG * 4;

    uint32_t* Ahs = smem_dyn;

    const int m0 = blockIdx.x * 64;
    const int tid = threadIdx.x, lane = tid & 31, wid = tid >> 5;
    const int wn = wid;               // 8 n-positions; tile j at col wn*8 + j*64

    const uint32_t sbase = (uint32_t)__cvta_generic_to_shared(smem_dyn);

    // ldmatrix lane addresses (stage 0)
    const int arowoff = ((lane >> 3) & 1) * 8 + (lane & 7);
    const int akoff   = (lane >> 4) * 4;
    uint32_t a_addr[4];
    #pragma unroll
    for (int mt = 0; mt < 4; mt++)
        a_addr[mt] = sbase + ((mt * 16 + arowoff) * SP + akoff) * 4;
    const uint32_t dAl = OA_L * 4;
    const int lb = lane & 15;
    uint32_t b_addr[4], bl_addr;
    #pragma unroll
    for (int j = 0; j < 4; j++)
        b_addr[j] = sbase + (OB_H + (wn * 8 + j * 64 + (lb & 7)) * SP
                             + ((lb >> 3) & 1) * 4) * 4;
    bl_addr = sbase + (OB_L + (wn * 8 + (lb & 7)) * SP + ((lb >> 3) & 1) * 4) * 4;

    // global-load coordinates
    const int ar = tid >> 3, afq = (tid & 7) * 4;   // A rows ar, ar+32
    const int aso = ar * SP + (afq >> 1);
    const int br = tid >> 2, bc = (tid & 3) * 4;    // B rows br + e*64

    float4 va[2];
    auto ldgA = [&](int k0) {
        #pragma unroll
        for (int e = 0; e < 2; e++)
            va[e] = *(const float4*)(xg + (long)(m0 + ar + e*32) * DD + k0 + afq);
    };
    auto cpB = [&](int k0, int s) {
        uint32_t d0 = sbase + (s * STG + OB_H + br * SP + bc) * 4;
        #pragma unroll
        for (int e = 0; e < 4; e++)
            cp16(d0 + e * 64 * SP * 4, &Wh[(br + e*64) * 512 + (k0 >> 1) + bc]);
        cp16(sbase + (s * STG + OB_L + br * SP + bc) * 4,
             &Wl[br * 512 + (k0 >> 1) + bc]);
        cp_commit();
    };
    auto stA = [&](int s) {
        #pragma unroll
        for (int e = 0; e < 2; e++) {
            float4 v = va[e];
            __nv_bfloat162 h0, l0, h1, l1;
            cvt_hilo(v.x, v.y, h0, l0);  cvt_hilo(v.z, v.w, h1, l1);
            int o = s * STG + aso + e * 32 * SP;
            Ahs[o]        = b2u(h0);  Ahs[o + 1]        = b2u(h1);
            Ahs[OA_L + o] = b2u(l0);  Ahs[OA_L + o + 1] = b2u(l1);
        }
    };

    float acc[4][4][4] = {};   // [m-subtile][j][frag]

    // prologue: fill stage 0
    ldgA(0);
    cpB(0, 0);
    stA(0);
    cp_wait0();
    __syncthreads();

    int s = 0;
    for (int k0 = 0; k0 < DD; k0 += 32, s ^= 1) {
        const bool more = (k0 + 32) < DD;
        if (more) {
            ldgA(k0 + 32);
            cpB(k0 + 32, s ^ 1);   // async fill of the other stage
        }

        const uint32_t so = s * STGB;
        #pragma unroll
        for (int kp = 0; kp < 2; kp++) {
            const uint32_t kb = so + kp * 32;
            uint32_t bh[4][2], bl2[2], ah[4][4];
            #pragma unroll
            for (int j = 0; j < 4; j++) ldmx2(bh[j], b_addr[j] + kb);
            ldmx2(bl2, bl_addr + kb);
            #pragma unroll
            for (int mt = 0; mt < 4; mt++) ldmx4(ah[mt], a_addr[mt] + kb);

            // 16 fully independent hh MMAs — no accumulator chains
            #pragma unroll
            for (int mt = 0; mt < 4; mt++)
                #pragma unroll
                for (int j = 0; j < 4; j++)
                    mma_bf16(acc[mt][j], ah[mt], bh[j]);

            // F lo-product pass: per mt {hl, lh}; chains across mt independent
            #pragma unroll
            for (int mt = 0; mt < 4; mt++) {
                uint32_t al4[4];
                ldmx4(al4, a_addr[mt] + dAl + kb);
                mma_bf16(acc[mt][2], ah[mt], bl2);    // hi*lo (F)
                mma_bf16(acc[mt][2], al4, bh[2]);     // lo*hi (F)
            }
        }

        if (more) stA(s ^ 1);   // convert+store A into the other stage
        cp_wait0();
        __syncthreads();        // ONE barrier per iteration
    }

    const int r4 = lane >> 2, c4 = lane & 3;
    #pragma unroll
    for (int mt = 0; mt < 4; mt++)
        #pragma unroll
        for (int j = 0; j < 4; j++) {
            int row = m0 + mt * 16 + r4;
            int col = wn * 8 + j * 64 + 2 * c4;
            *(float2*)(Cg + (long)row * 256 + col) =
                make_float2(acc[mt][j][0], acc[mt][j][1]);
            *(float2*)(Cg + (long)(row + 8) * 256 + col) =
                make_float2(acc[mt][j][2], acc[mt][j][3]);
        }
}

// ===========================================================================
// out_bf16: out[64,64 tile] = fc * W2^T, 3-product split, inputs already bf16.
// K=64 one-shot: 8 uint4 loads/thread, one sync, 12 k16-MMA steps, store.
// ===========================================================================
__global__ void __launch_bounds__(256)
out_bf16(const uint32_t* __restrict__ fcH, const uint32_t* __restrict__ fcL,
         const uint32_t* __restrict__ W2h, const uint32_t* __restrict__ W2l,
         float* __restrict__ Cg)
{
    constexpr int SP = 36;
    __shared__ uint32_t Ah[64*SP], Al[64*SP];
    __shared__ uint32_t Bh[64*SP], Bl[64*SP];

    const int n0 = blockIdx.x * 64;
    const int m0 = blockIdx.y * 64;
    const int tid = threadIdx.x, lane = tid & 31, wid = tid >> 5;
    const int wm0 = (wid & 1) * 32, wn0 = (wid >> 1) * 16;

    {
        #pragma unroll
        for (int e = 0; e < 2; e++) {
            int idx = tid + e * 256;
            int r = idx >> 3, c = (idx & 7) * 4;
            int o = r * SP + c;
            *(uint4*)&Ah[o] = *(const uint4*)&fcH[(long)(m0 + r) * 32 + c];
            *(uint4*)&Al[o] = *(const uint4*)&fcL[(long)(m0 + r) * 32 + c];
            *(uint4*)&Bh[o] = *(const uint4*)&W2h[(long)(n0 + r) * 32 + c];
            *(uint4*)&Bl[o] = *(const uint4*)&W2l[(long)(n0 + r) * 32 + c];
        }
    }
    __syncthreads();

    const int arowoff = ((lane >> 3) & 1) * 8 + (lane & 7);
    const int akoff   = (lane >> 4) * 4;
    uint32_t a_addr[2];
    #pragma unroll
    for (int mt = 0; mt < 2; mt++)
        a_addr[mt] = (uint32_t)__cvta_generic_to_shared(
            &Ah[(wm0 + mt * 16 + arowoff) * SP + akoff]);
    const int lb = lane & 15;
    uint32_t b_addr[2];
    #pragma unroll
    for (int nt = 0; nt < 2; nt++)
        b_addr[nt] = (uint32_t)__cvta_generic_to_shared(
            &Bh[(wn0 + nt * 8 + (lb & 7)) * SP + ((lb >> 3) & 1) * 4]);
    const uint32_t dAl = (uint32_t)((const char*)Al - (const char*)Ah);
    const uint32_t dBl = (uint32_t)((const char*)Bl - (const char*)Bh);

    float acc[2][2][4] = {};

    #pragma unroll
    for (int kp = 0; kp < 4; kp++) {
        const uint32_t kb = kp * 32;
        uint32_t ah[2][4], al[2][4], bh[2][2], bl[2][2];
        #pragma unroll
        for (int mt = 0; mt < 2; mt++) ldmx4(ah[mt], a_addr[mt] + kb);
        #pragma unroll
        for (int nt = 0; nt < 2; nt++) ldmx2(bh[nt], b_addr[nt] + kb);
        #pragma unroll
        for (int mt = 0; mt < 2; mt++) ldmx4(al[mt], a_addr[mt] + dAl + kb);
        #pragma unroll
        for (int nt = 0; nt < 2; nt++) ldmx2(bl[nt], b_addr[nt] + dBl + kb);
        #pragma unroll
        for (int mt = 0; mt < 2; mt++)
            #pragma unroll
            for (int nt = 0; nt < 2; nt++) {
                mma_bf16(acc[mt][nt], ah[mt], bh[nt]);
                mma_bf16(acc[mt][nt], ah[mt], bl[nt]);
                mma_bf16(acc[mt][nt], al[mt], bh[nt]);
            }
    }

    const int r4 = lane >> 2, c4 = lane & 3;
    #pragma unroll
    for (int mt = 0; mt < 2; mt++)
        #pragma unroll
        for (int nt = 0; nt < 2; nt++) {
            int row = m0 + wm0 + mt * 16 + r4;
            int col = n0 + wn0 + nt * 8 + 2 * c4;
            *(float2*)(Cg + (long)row * 1024 + col) =
                make_float2(acc[mt][nt][0], acc[mt][nt][1]);
            *(float2*)(Cg + (long)(row + 8) * 1024 + col) =
                make_float2(acc[mt][nt][2], acc[mt][nt][3]);
        }
}

// ===========================================================================
// Tensor GEMM (tf32), ATB form: C[64,N] = A[L,64]^T * B[L,N] over rows L.
// ===========================================================================
__global__ void __launch_bounds__(256)
tgemm_atb(const float* __restrict__ Ag, int lda, long sAb,
          const float* __restrict__ Bg, int ldb, long sBb,
          float* __restrict__ Cg, long sCb, long sCsplit, int ldc,
          int Lchunk)
{
    constexpr int BK = 16, LDT = 64 + 4;
    __shared__ float As[BK][LDT];
    __shared__ float Bs[BK][LDT];

    const int b = blockIdx.z, sp = blockIdx.y;
    const long l0b = (long)sp * Lchunk;
    Ag += (long)b * sAb;  Bg += (long)b * sBb;
    Cg += (long)b * sCb + (long)sp * sCsplit;
    const int n0 = blockIdx.x * 64;
    const int tid = threadIdx.x, lane = tid & 31, wid = tid >> 5;
    const int wm0 = (wid & 1) * 32, wn0 = (wid >> 1) * 16;
    const int r4 = lane >> 2, c4 = lane & 3;
    const int lrow = tid >> 4, lc4 = (tid & 15) * 4;

    float acc[2][2][4] = {};
    float4 va, vb;

    auto ldg = [&](int l0) {
        va = *(const float4*)(Ag + (l0b + l0 + lrow) * lda + lc4);
        vb = *(const float4*)(Bg + (l0b + l0 + lrow) * ldb + n0 + lc4);
    };
    auto store = [&]() {
        As[lrow][lc4+0] = tf32_rna(va.x);  As[lrow][lc4+1] = tf32_rna(va.y);
        As[lrow][lc4+2] = tf32_rna(va.z);  As[lrow][lc4+3] = tf32_rna(va.w);
        Bs[lrow][lc4+0] = tf32_rna(vb.x);  Bs[lrow][lc4+1] = tf32_rna(vb.y);
        Bs[lrow][lc4+2] = tf32_rna(vb.z);  Bs[lrow][lc4+3] = tf32_rna(vb.w);
    };

    ldg(0);
    store();
    __syncthreads();

    for (int l0 = 0; l0 < Lchunk; l0 += BK) {
        const bool more = (l0 + BK) < Lchunk;
        if (more) ldg(l0 + BK);

        #pragma unroll
        for (int kk = 0; kk < BK; kk += 8) {
            uint32_t af[2][4], bf[2][2];
            #pragma unroll
            for (int mt = 0; mt < 2; mt++) {
                int row = wm0 + mt*16 + r4;
                af[mt][0] = f2u(As[kk + c4    ][row    ]);
                af[mt][1] = f2u(As[kk + c4    ][row + 8]);
                af[mt][2] = f2u(As[kk + c4 + 4][row    ]);
                af[mt][3] = f2u(As[kk + c4 + 4][row + 8]);
            }
            #pragma unroll
            for (int nt = 0; nt < 2; nt++) {
                int col = wn0 + nt*8 + r4;
                bf[nt][0] = f2u(Bs[kk + c4    ][col]);
                bf[nt][1] = f2u(Bs[kk + c4 + 4][col]);
            }
            #pragma unroll
            for (int mt = 0; mt < 2; mt++)
                #pragma unroll
                for (int nt = 0; nt < 2; nt++)
                    mma_tf32(acc[mt][nt], af[mt][0], af[mt][1], af[mt][2], af[mt][3],
                             bf[nt][0], bf[nt][1]);
        }
        __syncthreads();
        if (more) {
            store();
            __syncthreads();
        }
    }
    #pragma unroll
    for (int mt = 0; mt < 2; mt++)
        #pragma unroll
        for (int nt = 0; nt < 2; nt++) {
            int row = wm0 + mt*16 + r4;
            int col = n0 + wn0 + nt*8 + 2*c4;
            *(float2*)(Cg + (long)row * ldc + col) =
                make_float2(acc[mt][nt][0], acc[mt][nt][1]);
            *(float2*)(Cg + (long)(row + 8) * ldc + col) =
                make_float2(acc[mt][nt][2], acc[mt][nt][3]);
        }
}

// ===========================================================================
// SIMT fp32 NN GEMM (U2 only): C[M,N] = A[M,K]*B[K,N], split-K via z
// ===========================================================================
template<int BM,int BN,int BK,int TM,int TN>
__global__ void __launch_bounds__((BM/TM)*(BN/TN))
gemm_nn(const float* __restrict__ A, long sA, int lda,
        const float* __restrict__ B, long sB, int ldb,
        float* __restrict__ C, long sC, int ldc,
        int K)
{
    constexpr int THREADS = (BM/TM)*(BN/TN);
    __shared__ float As[BK][BM];
    __shared__ float Bs[BK][BN];

    const int bz = blockIdx.z;
    A += bz * sA;  B += bz * sB;  C += bz * sC;

    const int m0 = blockIdx.y * BM;
    const int n0 = blockIdx.x * BN;
    const int tid = threadIdx.x;
    const int tx = tid % (BN/TN);
    const int ty = tid / (BN/TN);

    float acc[TM][TN];
    #pragma unroll
    for (int i = 0; i < TM; i++)
        #pragma unroll
        for (int j = 0; j < TN; j++) acc[i][j] = 0.f;

    for (int k0 = 0; k0 < K; k0 += BK) {
        #pragma unroll
        for (int e = 0; e < (BM*BK/4)/THREADS; e++) {
            int idx = tid + e*THREADS;
            int row = idx / (BK/4), cv = idx % (BK/4);
            float4 v = *(const float4*)(A + (long)(m0+row)*lda + k0 + cv*4);
            As[cv*4+0][row] = v.x;  As[cv*4+1][row] = v.y;
            As[cv*4+2][row] = v.z;  As[cv*4+3][row] = v.w;
        }
        #pragma unroll
        for (int e = 0; e < (BK*BN/4)/THREADS; e++) {
            int idx = tid + e*THREADS;
            int row = idx / (BN/4), cv = idx % (BN/4);
            *(float4*)&Bs[row][cv*4] =
                *(const float4*)(B + (long)(k0+row)*ldb + n0 + cv*4);
        }
        __syncthreads();
        #pragma unroll
        for (int k = 0; k < BK; k++) {
            float a[TM], b[TN];
            #pragma unroll
            for (int i = 0; i < TM; i += 4) *(float4*)(a+i) = *(const float4*)&As[k][ty*TM+i];
            #pragma unroll
            for (int j = 0; j < TN; j += 4) *(float4*)(b+j) = *(const float4*)&Bs[k][tx*TN+j];
            #pragma unroll
            for (int i = 0; i < TM; i++)
                #pragma unroll
                for (int j = 0; j < TN; j++) acc[i][j] += a[i]*b[j];
        }
        __syncthreads();
    }
    #pragma unroll
    for (int i = 0; i < TM; i++) {
        int row = m0 + ty*TM + i;
        #pragma unroll
        for (int j = 0; j < TN; j += 4) {
            float4 v;
            v.x = acc[i][j];   v.y = acc[i][j+1];
            v.z = acc[i][j+2]; v.w = acc[i][j+3];
            *(float4*)(C + (long)row*ldc + n0 + tx*TN + j) = v;
        }
    }
}

// ===========================================================================
// fc = F + Q @ T_b computed in fp32 (T_b summed inline from 32 L-split
// partials, same ascending order as the old reduceN), emitted as packed
// bf16 hi/lo k-pairs.
// ===========================================================================
__global__ void __launch_bounds__(256)
fc_kernel(const float* __restrict__ qkfp, const float* __restrict__ tpart,
          uint32_t* __restrict__ fcH, uint32_t* __restrict__ fcL)
{
    __shared__ float Qs[64][68];
    __shared__ float Ts[64][68];

    const int r0 = blockIdx.x * 64;
    const int b  = r0 / NSEQ;
    const int tid = threadIdx.x;

    #pragma unroll
    for (int e = 0; e < 4; e++) {
        int idx = tid + e * 256;
        int row = idx >> 4, fq = idx & 15;
        float4 q = *(const float4*)(qkfp + (long)(r0 + row) * 256 + fq * 4);
        *(float4*)&Qs[row][fq * 4] = q;
        // T_b = sum of 32 partials (ascending s — matches reduceN order)
        float4 t = make_float4(0.f, 0.f, 0.f, 0.f);
        const float* tp = tpart + (long)b * 4096 + row * 64 + fq * 4;
        for (int s = 0; s < 32; s++) {
            float4 p = *(const float4*)(tp + (long)s * BB * 4096);
            t.x += p.x;  t.y += p.y;  t.z += p.z;  t.w += p.w;
        }
        *(float4*)&Ts[row][fq * 4] = t;
    }
    __syncthreads();

    const int row = tid >> 2;
    const int col0 = (tid & 3) * 16;
    float acc[16];
    #pragma unroll
    for (int j = 0; j < 16; j += 4) {
        float4 f = *(const float4*)(qkfp + (long)(r0 + row) * 256 + 128 + col0 + j);
        acc[j] = f.x; acc[j+1] = f.y; acc[j+2] = f.z; acc[j+3] = f.w;
    }
    #pragma unroll 8
    for (int k = 0; k < 64; k++) {
        float q = Qs[row][k];
        #pragma unroll
        for (int j = 0; j < 16; j += 4) {
            float4 t = *(const float4*)&Ts[k][col0 + j];
            acc[j]   += q * t.x;  acc[j+1] += q * t.y;
            acc[j+2] += q * t.z;  acc[j+3] += q * t.w;
        }
    }
    const long obase = (long)(r0 + row) * 32 + (col0 >> 1);
    #pragma unroll
    for (int jj = 0; jj < 8; jj++) {
        __nv_bfloat162 h, l;
        cvt_hilo(acc[2*jj], acc[2*jj + 1], h, l);
        fcH[obase + jj] = b2u(h);
        fcL[obase + jj] = b2u(l);
    }
}

// ============================================================================
extern "C" void kernel_launch(void* const* d_in, const int* in_sizes, int n_in,
                              void* d_out, int out_size)
{
    const float* x  = (const float*)d_in[0];   // [8,2048,1024]
    const float* Wq = (const float*)d_in[1];   // [64,1024]
    const float* Wk = (const float*)d_in[2];   // [64,1024]
    const float* Wv = (const float*)d_in[3];   // [1024,1024]
    const float* W1 = (const float*)d_in[4];   // [64,1024]
    const float* W2 = (const float*)d_in[5];   // [1024,64]
    float* out = (float*)d_out;                // [8,2048,1024]

    float *qkfp, *u2p, *tpart;
    uint32_t *wh, *wl, *fcH, *fcL, *w2h, *w2l;
    cudaGetSymbolAddress((void**)&qkfp,  g_QKFP);
    cudaGetSymbolAddress((void**)&u2p,   g_U2part);
    cudaGetSymbolAddress((void**)&tpart, g_Tpart);
    cudaGetSymbolAddress((void**)&wh,    g_Wh);
    cudaGetSymbolAddress((void**)&wl,    g_Wl);
    cudaGetSymbolAddress((void**)&fcH,   g_fcH);
    cudaGetSymbolAddress((void**)&fcL,   g_fcL);
    cudaGetSymbolAddress((void**)&w2h,   g_W2h);
    cudaGetSymbolAddress((void**)&w2l,   g_W2l);

    // allow 70KB dynamic smem for qkfp_fused (2 stages x 35840B)
    static_assert(2 * 8960 * 4 == 71680, "stage size");
    cudaFuncSetAttribute(qkfp_fused,
                         cudaFuncAttributeMaxDynamicSharedMemorySize, 71680);

    // U2 = W1 @ Wv : [64,1024], 32-way split-K partials
    gemm_nn<64,64,16,4,4><<<dim3(16,1,32), 256>>>(
        W1, 32, DD,  Wv, (long)32*DD, DD,  u2p, (long)DKK*DD, DD,  32);

    // Build all bf16 weight planes (folds memcpys + U2 reduce + conversions)
    prep_w<<<(256*512 + 1024*32 + 255)/256, 256>>>(
        Wq, Wk, W1, u2p, W2, wh, wl, w2h, w2l);

    // QKFP = x @ Wext^T : one pass over x, F columns split, 2 blocks/SM
    qkfp_fused<<<256, 256, 71680>>>(x, wh, wl, qkfp);

    // T_b partials = K_b^T P_b : [32 splits][8,64,64]  (tf32, 32-way L-split)
    tgemm_atb<<<dim3(1, 32, 8), 256>>>(
        qkfp + 64,  256, (long)NSEQ*256,
        qkfp + 192, 256, (long)NSEQ*256,
        tpart, (long)DKK*DKK, (long)BB*DKK*DKK, DKK,
        NSEQ/32);

    // fc = F + Q @ T (T reduced inline) -> bf16 hi/lo
    fc_kernel<<<MTOT/64, 256>>>(qkfp, tpart, fcH, fcL);

    // out = fc @ W2^T : all-bf16 one-shot, split everywhere
    out_bf16<<<dim3(16, 256), 256>>>(fcH, fcL, w2h, w2l, out);
}

// round 12
// speedup vs baseline: 1.0482x; 1.0482x over previous
#include <cuda_runtime.h>
#include <cuda_bf16.h>
#include <cstdint>

// Problem dims (fixed by the dataset)
#define BB 8
#define NSEQ 2048
#define DD 1024
#define DKK 64
#define MTOT (BB*NSEQ)   // 16384

// ---------------- scratch (static __device__ — no allocation) ----------------
__device__ float    g_QKFP[(long)MTOT*256];  // Q[0:64] K[64:128] F[128:192] P[192:256]
__device__ float    g_U2part[32*DKK*DD];     // split-K partials of U2
__device__ float    g_Tpart[64*BB*DKK*DKK];  // split-L partials of T
__device__ float    g_T[BB*DKK*DKK];         // reduced T
__device__ uint32_t g_Wh[256*512];           // Wext bf16-hi, packed k-pairs
__device__ uint32_t g_Wl[64*512];            // Wext bf16-lo, rows 128..191 (W1)
__device__ uint32_t g_fcH[(long)MTOT*32];    // fc bf16-hi packed
__device__ uint32_t g_fcL[(long)MTOT*32];    // fc bf16-lo packed
__device__ uint32_t g_W2h[1024*32];          // W2 bf16-hi packed
__device__ uint32_t g_W2l[1024*32];          // W2 bf16-lo packed

// ---------------------------------------------------------------------------
// helpers
// ---------------------------------------------------------------------------
__device__ __forceinline__ float tf32_rna(float x) {
    uint32_t r;
    asm("cvt.rna.tf32.f32 %0, %1;" : "=r"(r) : "f"(x));
    return __uint_as_float(r);
}
__device__ __forceinline__ uint32_t f2u(float f) { return __float_as_uint(f); }
__device__ __forceinline__ uint32_t b2u(__nv_bfloat162 v) {
    return *reinterpret_cast<uint32_t*>(&v);
}
__device__ __forceinline__ void cvt_hilo(float x, float y,
                                         __nv_bfloat162& h, __nv_bfloat162& l)
{
    h = __floats2bfloat162_rn(x, y);
    l = __floats2bfloat162_rn(x - __bfloat162float(h.x), y - __bfloat162float(h.y));
}

__device__ __forceinline__ void mma_tf32(float (&d)[4],
    uint32_t a0, uint32_t a1, uint32_t a2, uint32_t a3,
    uint32_t b0, uint32_t b1)
{
    asm volatile(
        "mma.sync.aligned.m16n8k8.row.col.f32.tf32.tf32.f32 "
        "{%0,%1,%2,%3},{%4,%5,%6,%7},{%8,%9},{%0,%1,%2,%3};"
        : "+f"(d[0]), "+f"(d[1]), "+f"(d[2]), "+f"(d[3])
        : "r"(a0), "r"(a1), "r"(a2), "r"(a3), "r"(b0), "r"(b1));
}

__device__ __forceinline__ void mma_bf16(float (&d)[4],
    const uint32_t (&a)[4], const uint32_t (&b)[2])
{
    asm volatile(
        "mma.sync.aligned.m16n8k16.row.col.f32.bf16.bf16.f32 "
        "{%0,%1,%2,%3},{%4,%5,%6,%7},{%8,%9},{%0,%1,%2,%3};"
        : "+f"(d[0]), "+f"(d[1]), "+f"(d[2]), "+f"(d[3])
        : "r"(a[0]), "r"(a[1]), "r"(a[2]), "r"(a[3]), "r"(b[0]), "r"(b[1]));
}

__device__ __forceinline__ void ldmx4(uint32_t (&r)[4], uint32_t addr) {
    asm volatile("ldmatrix.sync.aligned.m8n8.x4.shared.b16 {%0,%1,%2,%3}, [%4];"
        : "=r"(r[0]), "=r"(r[1]), "=r"(r[2]), "=r"(r[3]) : "r"(addr));
}
__device__ __forceinline__ void ldmx2(uint32_t (&r)[2], uint32_t addr) {
    asm volatile("ldmatrix.sync.aligned.m8n8.x2.shared.b16 {%0,%1}, [%2];"
        : "=r"(r[0]), "=r"(r[1]) : "r"(addr));
}

__device__ __forceinline__ void cp16(uint32_t smem_addr, const void* gptr) {
    asm volatile("cp.async.cg.shared.global [%0], [%1], 16;"
        :: "r"(smem_addr), "l"(gptr));
}
__device__ __forceinline__ void cp_commit() {
    asm volatile("cp.async.commit_group;" ::: "memory");
}
__device__ __forceinline__ void cp_wait0() {
    asm volatile("cp.async.wait_group 0;" ::: "memory");
}

// ===========================================================================
// prep_w: builds bf16 weight planes directly from the inputs.
// Wh rows: 0..63 Wq, 64..127 Wk, 128..191 W1 (lo plane -> Wl), 192..255 U2
// (U2 summed inline from the 32 split-K partials — same order as reduceN).
// Also converts W2 -> W2h/W2l.
// ===========================================================================
__global__ void prep_w(const float* __restrict__ Wq, const float* __restrict__ Wk,
                       const float* __restrict__ W1, const float* __restrict__ u2p,
                       const float* __restrict__ W2,
                       uint32_t* __restrict__ Wh, uint32_t* __restrict__ Wl,
                       uint32_t* __restrict__ W2h, uint32_t* __restrict__ W2l)
{
    int i = blockIdx.x * 256 + threadIdx.x;
    if (i < 256*512) {
        int row = i >> 9, p = i & 511;
        float x, y;
        if (row < 128) {
            const float* W = (row < 64) ? Wq : Wk;
            int r = row & 63;
            x = W[r*DD + 2*p];  y = W[r*DD + 2*p + 1];
        } else if (row < 192) {
            int r = row - 128;
            x = W1[r*DD + 2*p];  y = W1[r*DD + 2*p + 1];
        } else {
            int r = row - 192;
            float sx = 0.f, sy = 0.f;
            for (int s = 0; s < 32; s++) {
                sx += u2p[(long)s*DKK*DD + r*DD + 2*p];
                sy += u2p[(long)s*DKK*DD + r*DD + 2*p + 1];
            }
            x = sx;  y = sy;
        }
        __nv_bfloat162 h, l;
        cvt_hilo(x, y, h, l);
        Wh[i] = b2u(h);
        if (row >= 128 && row < 192) Wl[(row - 128) * 512 + p] = b2u(l);
    } else {
        int j = i - 256*512;
        if (j < 1024*32) {
            __nv_bfloat162 h, l;
            cvt_hilo(W2[2*j], W2[2*j + 1], h, l);
            W2h[j] = b2u(h);
            W2l[j] = b2u(l);
        }
    }
}

// ===========================================================================
// qkfp_fused: C[M,256] = x[M,1024] * Wext[256,1024]^T, ONE pass over x.
// F n-tile (j==2) gets the 3-product hi/lo split. BM=64, BN=256, BK=32,
// 256 threads (8 warps on n), 2 blocks/SM, grid=256 = one wave on 148 SMs.
// 2-stage double-buffered dynamic smem (70KB), ONE __syncthreads per iter.
// MMA ordering: all-fragments load -> 16 independent hh MMAs -> F lo pass.
// Stage layout (uint32): Ah[0,1280) Al[1280,2560) Bh[2560,7680) Bl[7680,8960)
// ===========================================================================
extern __shared__ uint32_t smem_dyn[];

__global__ void __launch_bounds__(256, 2)
qkfp_fused(const float* __restrict__ xg, const uint32_t* __restrict__ Wh,
           const uint32_t* __restrict__ Wl, float* __restrict__ Cg)
{
    constexpr int SP = 20;            // uint32 per smem row (80B) — conflict-free
    constexpr int OA_L = 1280;
    constexpr int OB_H = 2560;
    constexpr int OB_L = 7680;
    constexpr int STG  = 8960;        // stage stride in uint32
    constexpr uint32_t STGB = STG * 4;

    uint32_t* Ahs = smem_dyn;

    const int m0 = blockIdx.x * 64;
    const int tid = threadIdx.x, lane = tid & 31, wid = tid >> 5;
    const int wn = wid;               // 8 n-positions; tile j at col wn*8 + j*64

    const uint32_t sbase = (uint32_t)__cvta_generic_to_shared(smem_dyn);

    // ldmatrix lane addresses (stage 0)
    const int arowoff = ((lane >> 3) & 1) * 8 + (lane & 7);
    const int akoff   = (lane >> 4) * 4;
    uint32_t a_addr[4];
    #pragma unroll
    for (int mt = 0; mt < 4; mt++)
        a_addr[mt] = sbase + ((mt * 16 + arowoff) * SP + akoff) * 4;
    const uint32_t dAl = OA_L * 4;
    const int lb = lane & 15;
    uint32_t b_addr[4], bl_addr;
    #pragma unroll
    for (int j = 0; j < 4; j++)
        b_addr[j] = sbase + (OB_H + (wn * 8 + j * 64 + (lb & 7)) * SP
                             + ((lb >> 3) & 1) * 4) * 4;
    bl_addr = sbase + (OB_L + (wn * 8 + (lb & 7)) * SP + ((lb >> 3) & 1) * 4) * 4;

    // global-load coordinates
    const int ar = tid >> 3, afq = (tid & 7) * 4;   // A rows ar, ar+32
    const int aso = ar * SP + (afq >> 1);
    const int br = tid >> 2, bc = (tid & 3) * 4;    // B rows br + e*64

    float4 va[2];
    auto ldgA = [&](int k0) {
        #pragma unroll
        for (int e = 0; e < 2; e++)
            va[e] = *(const float4*)(xg + (long)(m0 + ar + e*32) * DD + k0 + afq);
    };
    auto cpB = [&](int k0, int s) {
        uint32_t d0 = sbase + (s * STG + OB_H + br * SP + bc) * 4;
        #pragma unroll
        for (int e = 0; e < 4; e++)
            cp16(d0 + e * 64 * SP * 4, &Wh[(br + e*64) * 512 + (k0 >> 1) + bc]);
        cp16(sbase + (s * STG + OB_L + br * SP + bc) * 4,
             &Wl[br * 512 + (k0 >> 1) + bc]);
        cp_commit();
    };
    auto stA = [&](int s) {
        #pragma unroll
        for (int e = 0; e < 2; e++) {
            float4 v = va[e];
            __nv_bfloat162 h0, l0, h1, l1;
            cvt_hilo(v.x, v.y, h0, l0);  cvt_hilo(v.z, v.w, h1, l1);
            int o = s * STG + aso + e * 32 * SP;
            Ahs[o]        = b2u(h0);  Ahs[o + 1]        = b2u(h1);
            Ahs[OA_L + o] = b2u(l0);  Ahs[OA_L + o + 1] = b2u(l1);
        }
    };

    float acc[4][4][4] = {};   // [m-subtile][j][frag]

    // prologue: fill stage 0
    ldgA(0);
    cpB(0, 0);
    stA(0);
    cp_wait0();
    __syncthreads();

    int s = 0;
    for (int k0 = 0; k0 < DD; k0 += 32, s ^= 1) {
        const bool more = (k0 + 32) < DD;
        if (more) {
            ldgA(k0 + 32);
            cpB(k0 + 32, s ^ 1);   // async fill of the other stage
        }

        const uint32_t so = s * STGB;
        #pragma unroll
        for (int kp = 0; kp < 2; kp++) {
            const uint32_t kb = so + kp * 32;
            uint32_t bh[4][2], bl2[2], ah[4][4];
            #pragma unroll
            for (int j = 0; j < 4; j++) ldmx2(bh[j], b_addr[j] + kb);
            ldmx2(bl2, bl_addr + kb);
            #pragma unroll
            for (int mt = 0; mt < 4; mt++) ldmx4(ah[mt], a_addr[mt] + kb);

            // 16 fully independent hh MMAs — no accumulator chains
            #pragma unroll
            for (int mt = 0; mt < 4; mt++)
                #pragma unroll
                for (int j = 0; j < 4; j++)
                    mma_bf16(acc[mt][j], ah[mt], bh[j]);

            // F lo-product pass: per mt {hl, lh}; chains across mt independent
            #pragma unroll
            for (int mt = 0; mt < 4; mt++) {
                uint32_t al4[4];
                ldmx4(al4, a_addr[mt] + dAl + kb);
                mma_bf16(acc[mt][2], ah[mt], bl2);    // hi*lo (F)
                mma_bf16(acc[mt][2], al4, bh[2]);     // lo*hi (F)
            }
        }

        if (more) stA(s ^ 1);   // convert+store A into the other stage
        cp_wait0();
        __syncthreads();        // ONE barrier per iteration
    }

    const int r4 = lane >> 2, c4 = lane & 3;
    #pragma unroll
    for (int mt = 0; mt < 4; mt++)
        #pragma unroll
        for (int j = 0; j < 4; j++) {
            int row = m0 + mt * 16 + r4;
            int col = wn * 8 + j * 64 + 2 * c4;
            *(float2*)(Cg + (long)row * 256 + col) =
                make_float2(acc[mt][j][0], acc[mt][j][1]);
            *(float2*)(Cg + (long)(row + 8) * 256 + col) =
                make_float2(acc[mt][j][2], acc[mt][j][3]);
        }
}

// ===========================================================================
// out_bf16: out[64,64 tile] = fc * W2^T, 3-product split, inputs already bf16.
// K=64 one-shot: 8 uint4 loads/thread, one sync, 12 k16-MMA steps, store.
// ===========================================================================
__global__ void __launch_bounds__(256)
out_bf16(const uint32_t* __restrict__ fcH, const uint32_t* __restrict__ fcL,
         const uint32_t* __restrict__ W2h, const uint32_t* __restrict__ W2l,
         float* __restrict__ Cg)
{
    constexpr int SP = 36;
    __shared__ uint32_t Ah[64*SP], Al[64*SP];
    __shared__ uint32_t Bh[64*SP], Bl[64*SP];

    const int n0 = blockIdx.x * 64;
    const int m0 = blockIdx.y * 64;
    const int tid = threadIdx.x, lane = tid & 31, wid = tid >> 5;
    const int wm0 = (wid & 1) * 32, wn0 = (wid >> 1) * 16;

    {
        #pragma unroll
        for (int e = 0; e < 2; e++) {
            int idx = tid + e * 256;
            int r = idx >> 3, c = (idx & 7) * 4;
            int o = r * SP + c;
            *(uint4*)&Ah[o] = *(const uint4*)&fcH[(long)(m0 + r) * 32 + c];
            *(uint4*)&Al[o] = *(const uint4*)&fcL[(long)(m0 + r) * 32 + c];
            *(uint4*)&Bh[o] = *(const uint4*)&W2h[(long)(n0 + r) * 32 + c];
            *(uint4*)&Bl[o] = *(const uint4*)&W2l[(long)(n0 + r) * 32 + c];
        }
    }
    __syncthreads();

    const int arowoff = ((lane >> 3) & 1) * 8 + (lane & 7);
    const int akoff   = (lane >> 4) * 4;
    uint32_t a_addr[2];
    #pragma unroll
    for (int mt = 0; mt < 2; mt++)
        a_addr[mt] = (uint32_t)__cvta_generic_to_shared(
            &Ah[(wm0 + mt * 16 + arowoff) * SP + akoff]);
    const int lb = lane & 15;
    uint32_t b_addr[2];
    #pragma unroll
    for (int nt = 0; nt < 2; nt++)
        b_addr[nt] = (uint32_t)__cvta_generic_to_shared(
            &Bh[(wn0 + nt * 8 + (lb & 7)) * SP + ((lb >> 3) & 1) * 4]);
    const uint32_t dAl = (uint32_t)((const char*)Al - (const char*)Ah);
    const uint32_t dBl = (uint32_t)((const char*)Bl - (const char*)Bh);

    float acc[2][2][4] = {};

    #pragma unroll
    for (int kp = 0; kp < 4; kp++) {
        const uint32_t kb = kp * 32;
        uint32_t ah[2][4], al[2][4], bh[2][2], bl[2][2];
        #pragma unroll
        for (int mt = 0; mt < 2; mt++) ldmx4(ah[mt], a_addr[mt] + kb);
        #pragma unroll
        for (int nt = 0; nt < 2; nt++) ldmx2(bh[nt], b_addr[nt] + kb);
        #pragma unroll
        for (int mt = 0; mt < 2; mt++) ldmx4(al[mt], a_addr[mt] + dAl + kb);
        #pragma unroll
        for (int nt = 0; nt < 2; nt++) ldmx2(bl[nt], b_addr[nt] + dBl + kb);
        #pragma unroll
        for (int mt = 0; mt < 2; mt++)
            #pragma unroll
            for (int nt = 0; nt < 2; nt++) {
                mma_bf16(acc[mt][nt], ah[mt], bh[nt]);
                mma_bf16(acc[mt][nt], ah[mt], bl[nt]);
                mma_bf16(acc[mt][nt], al[mt], bh[nt]);
            }
    }

    const int r4 = lane >> 2, c4 = lane & 3;
    #pragma unroll
    for (int mt = 0; mt < 2; mt++)
        #pragma unroll
        for (int nt = 0; nt < 2; nt++) {
            int row = m0 + wm0 + mt * 16 + r4;
            int col = n0 + wn0 + nt * 8 + 2 * c4;
            *(float2*)(Cg + (long)row * 1024 + col) =
                make_float2(acc[mt][nt][0], acc[mt][nt][1]);
            *(float2*)(Cg + (long)(row + 8) * 1024 + col) =
                make_float2(acc[mt][nt][2], acc[mt][nt][3]);
        }
}

// ===========================================================================
// Tensor GEMM (tf32), ATB form: C[64,N] = A[L,64]^T * B[L,N] over rows L.
// ===========================================================================
__global__ void __launch_bounds__(256)
tgemm_atb(const float* __restrict__ Ag, int lda, long sAb,
          const float* __restrict__ Bg, int ldb, long sBb,
          float* __restrict__ Cg, long sCb, long sCsplit, int ldc,
          int Lchunk)
{
    constexpr int BK = 16, LDT = 64 + 4;
    __shared__ float As[BK][LDT];
    __shared__ float Bs[BK][LDT];

    const int b = blockIdx.z, sp = blockIdx.y;
    const long l0b = (long)sp * Lchunk;
    Ag += (long)b * sAb;  Bg += (long)b * sBb;
    Cg += (long)b * sCb + (long)sp * sCsplit;
    const int n0 = blockIdx.x * 64;
    const int tid = threadIdx.x, lane = tid & 31, wid = tid >> 5;
    const int wm0 = (wid & 1) * 32, wn0 = (wid >> 1) * 16;
    const int r4 = lane >> 2, c4 = lane & 3;
    const int lrow = tid >> 4, lc4 = (tid & 15) * 4;

    float acc[2][2][4] = {};
    float4 va, vb;

    auto ldg = [&](int l0) {
        va = *(const float4*)(Ag + (l0b + l0 + lrow) * lda + lc4);
        vb = *(const float4*)(Bg + (l0b + l0 + lrow) * ldb + n0 + lc4);
    };
    auto store = [&]() {
        As[lrow][lc4+0] = tf32_rna(va.x);  As[lrow][lc4+1] = tf32_rna(va.y);
        As[lrow][lc4+2] = tf32_rna(va.z);  As[lrow][lc4+3] = tf32_rna(va.w);
        Bs[lrow][lc4+0] = tf32_rna(vb.x);  Bs[lrow][lc4+1] = tf32_rna(vb.y);
        Bs[lrow][lc4+2] = tf32_rna(vb.z);  Bs[lrow][lc4+3] = tf32_rna(vb.w);
    };

    ldg(0);
    store();
    __syncthreads();

    for (int l0 = 0; l0 < Lchunk; l0 += BK) {
        const bool more = (l0 + BK) < Lchunk;
        if (more) ldg(l0 + BK);

        #pragma unroll
        for (int kk = 0; kk < BK; kk += 8) {
            uint32_t af[2][4], bf[2][2];
            #pragma unroll
            for (int mt = 0; mt < 2; mt++) {
                int row = wm0 + mt*16 + r4;
                af[mt][0] = f2u(As[kk + c4    ][row    ]);
                af[mt][1] = f2u(As[kk + c4    ][row + 8]);
                af[mt][2] = f2u(As[kk + c4 + 4][row    ]);
                af[mt][3] = f2u(As[kk + c4 + 4][row + 8]);
            }
            #pragma unroll
            for (int nt = 0; nt < 2; nt++) {
                int col = wn0 + nt*8 + r4;
                bf[nt][0] = f2u(Bs[kk + c4    ][col]);
                bf[nt][1] = f2u(Bs[kk + c4 + 4][col]);
            }
            #pragma unroll
            for (int mt = 0; mt < 2; mt++)
                #pragma unroll
                for (int nt = 0; nt < 2; nt++)
                    mma_tf32(acc[mt][nt], af[mt][0], af[mt][1], af[mt][2], af[mt][3],
                             bf[nt][0], bf[nt][1]);
        }
        __syncthreads();
        if (more) {
            store();
            __syncthreads();
        }
    }
    #pragma unroll
    for (int mt = 0; mt < 2; mt++)
        #pragma unroll
        for (int nt = 0; nt < 2; nt++) {
            int row = wm0 + mt*16 + r4;
            int col = n0 + wn0 + nt*8 + 2*c4;
            *(float2*)(Cg + (long)row * ldc + col) =
                make_float2(acc[mt][nt][0], acc[mt][nt][1]);
            *(float2*)(Cg + (long)(row + 8) * ldc + col) =
                make_float2(acc[mt][nt][2], acc[mt][nt][3]);
        }
}

// ===========================================================================
// SIMT fp32 NN GEMM (U2 only): C[M,N] = A[M,K]*B[K,N], split-K via z
// ===========================================================================
template<int BM,int BN,int BK,int TM,int TN>
__global__ void __launch_bounds__((BM/TM)*(BN/TN))
gemm_nn(const float* __restrict__ A, long sA, int lda,
        const float* __restrict__ B, long sB, int ldb,
        float* __restrict__ C, long sC, int ldc,
        int K)
{
    constexpr int THREADS = (BM/TM)*(BN/TN);
    __shared__ float As[BK][BM];
    __shared__ float Bs[BK][BN];

    const int bz = blockIdx.z;
    A += bz * sA;  B += bz * sB;  C += bz * sC;

    const int m0 = blockIdx.y * BM;
    const int n0 = blockIdx.x * BN;
    const int tid = threadIdx.x;
    const int tx = tid % (BN/TN);
    const int ty = tid / (BN/TN);

    float acc[TM][TN];
    #pragma unroll
    for (int i = 0; i < TM; i++)
        #pragma unroll
        for (int j = 0; j < TN; j++) acc[i][j] = 0.f;

    for (int k0 = 0; k0 < K; k0 += BK) {
        #pragma unroll
        for (int e = 0; e < (BM*BK/4)/THREADS; e++) {
            int idx = tid + e*THREADS;
            int row = idx / (BK/4), cv = idx % (BK/4);
            float4 v = *(const float4*)(A + (long)(m0+row)*lda + k0 + cv*4);
            As[cv*4+0][row] = v.x;  As[cv*4+1][row] = v.y;
            As[cv*4+2][row] = v.z;  As[cv*4+3][row] = v.w;
        }
        #pragma unroll
        for (int e = 0; e < (BK*BN/4)/THREADS; e++) {
            int idx = tid + e*THREADS;
            int row = idx / (BN/4), cv = idx % (BN/4);
            *(float4*)&Bs[row][cv*4] =
                *(const float4*)(B + (long)(k0+row)*ldb + n0 + cv*4);
        }
        __syncthreads();
        #pragma unroll
        for (int k = 0; k < BK; k++) {
            float a[TM], b[TN];
            #pragma unroll
            for (int i = 0; i < TM; i += 4) *(float4*)(a+i) = *(const float4*)&As[k][ty*TM+i];
            #pragma unroll
            for (int j = 0; j < TN; j += 4) *(float4*)(b+j) = *(const float4*)&Bs[k][tx*TN+j];
            #pragma unroll
            for (int i = 0; i < TM; i++)
                #pragma unroll
                for (int j = 0; j < TN; j++) acc[i][j] += a[i]*b[j];
        }
        __syncthreads();
    }
    #pragma unroll
    for (int i = 0; i < TM; i++) {
        int row = m0 + ty*TM + i;
        #pragma unroll
        for (int j = 0; j < TN; j += 4) {
            float4 v;
            v.x = acc[i][j];   v.y = acc[i][j+1];
            v.z = acc[i][j+2]; v.w = acc[i][j+3];
            *(float4*)(C + (long)row*ldc + n0 + tx*TN + j) = v;
        }
    }
}

// Sum S split partials
template<int S>
__global__ void reduceN(const float* __restrict__ p, float* __restrict__ o, int n)
{
    int i = blockIdx.x * 256 + threadIdx.x;
    if (i < n) {
        float s = 0.f;
        #pragma unroll
        for (int j = 0; j < S; j++) s += p[i + (long)j * n];
        o[i] = s;
    }
}

// ===========================================================================
// fc = F + Q @ T_b computed in fp32 (T pre-reduced), emitted as packed
// bf16 hi/lo k-pairs.
// ===========================================================================
__global__ void __launch_bounds__(256)
fc_kernel(const float* __restrict__ qkfp, const float* __restrict__ T,
          uint32_t* __restrict__ fcH, uint32_t* __restrict__ fcL)
{
    __shared__ float Qs[64][68];
    __shared__ float Ts[64][68];

    const int r0 = blockIdx.x * 64;
    const int b  = r0 / NSEQ;
    const int tid = threadIdx.x;

    #pragma unroll
    for (int e = 0; e < 4; e++) {
        int idx = tid + e * 256;
        int row = idx >> 4, fq = idx & 15;
        float4 q = *(const float4*)(qkfp + (long)(r0 + row) * 256 + fq * 4);
        *(float4*)&Qs[row][fq * 4] = q;
        float4 t = *(const float4*)(T + (long)b * 4096 + row * 64 + fq * 4);
        *(float4*)&Ts[row][fq * 4] = t;
    }
    __syncthreads();

    const int row = tid >> 2;
    const int col0 = (tid & 3) * 16;
    float acc[16];
    #pragma unroll
    for (int j = 0; j < 16; j += 4) {
        float4 f = *(const float4*)(qkfp + (long)(r0 + row) * 256 + 128 + col0 + j);
        acc[j] = f.x; acc[j+1] = f.y; acc[j+2] = f.z; acc[j+3] = f.w;
    }
    #pragma unroll 8
    for (int k = 0; k < 64; k++) {
        float q = Qs[row][k];
        #pragma unroll
        for (int j = 0; j < 16; j += 4) {
            float4 t = *(const float4*)&Ts[k][col0 + j];
            acc[j]   += q * t.x;  acc[j+1] += q * t.y;
            acc[j+2] += q * t.z;  acc[j+3] += q * t.w;
        }
    }
    const long obase = (long)(r0 + row) * 32 + (col0 >> 1);
    #pragma unroll
    for (int jj = 0; jj < 8; jj++) {
        __nv_bfloat162 h, l;
        cvt_hilo(acc[2*jj], acc[2*jj + 1], h, l);
        fcH[obase + jj] = b2u(h);
        fcL[obase + jj] = b2u(l);
    }
}

// ============================================================================
extern "C" void kernel_launch(void* const* d_in, const int* in_sizes, int n_in,
                              void* d_out, int out_size)
{
    const float* x  = (const float*)d_in[0];   // [8,2048,1024]
    const float* Wq = (const float*)d_in[1];   // [64,1024]
    const float* Wk = (const float*)d_in[2];   // [64,1024]
    const float* Wv = (const float*)d_in[3];   // [1024,1024]
    const float* W1 = (const float*)d_in[4];   // [64,1024]
    const float* W2 = (const float*)d_in[5];   // [1024,64]
    float* out = (float*)d_out;                // [8,2048,1024]

    float *qkfp, *u2p, *tpart, *gt;
    uint32_t *wh, *wl, *fcH, *fcL, *w2h, *w2l;
    cudaGetSymbolAddress((void**)&qkfp,  g_QKFP);
    cudaGetSymbolAddress((void**)&u2p,   g_U2part);
    cudaGetSymbolAddress((void**)&tpart, g_Tpart);
    cudaGetSymbolAddress((void**)&gt,    g_T);
    cudaGetSymbolAddress((void**)&wh,    g_Wh);
    cudaGetSymbolAddress((void**)&wl,    g_Wl);
    cudaGetSymbolAddress((void**)&fcH,   g_fcH);
    cudaGetSymbolAddress((void**)&fcL,   g_fcL);
    cudaGetSymbolAddress((void**)&w2h,   g_W2h);
    cudaGetSymbolAddress((void**)&w2l,   g_W2l);

    // allow 70KB dynamic smem for qkfp_fused (2 stages x 35840B)
    static_assert(2 * 8960 * 4 == 71680, "stage size");
    cudaFuncSetAttribute(qkfp_fused,
                         cudaFuncAttributeMaxDynamicSharedMemorySize, 71680);

    // U2 = W1 @ Wv : [64,1024], 32-way split-K partials
    gemm_nn<64,64,16,4,4><<<dim3(16,1,32), 256>>>(
        W1, 32, DD,  Wv, (long)32*DD, DD,  u2p, (long)DKK*DD, DD,  32);

    // Build all bf16 weight planes (folds memcpys + U2 reduce + conversions)
    prep_w<<<(256*512 + 1024*32 + 255)/256, 256>>>(
        Wq, Wk, W1, u2p, W2, wh, wl, w2h, w2l);

    // QKFP = x @ Wext^T : one pass over x, F columns split, 2 blocks/SM
    qkfp_fused<<<256, 256, 71680>>>(x, wh, wl, qkfp);

    // T_b partials = K_b^T P_b : 64-way L-split (latency-bound fix)
    tgemm_atb<<<dim3(1, 64, 8), 256>>>(
        qkfp + 64,  256, (long)NSEQ*256,
        qkfp + 192, 256, (long)NSEQ*256,
        tpart, (long)DKK*DKK, (long)BB*DKK*DKK, DKK,
        NSEQ/64);
    reduceN<64><<<(BB*DKK*DKK + 255)/256, 256>>>(tpart, gt, BB*DKK*DKK);

    // fc = F + Q @ T -> bf16 hi/lo  (reads pre-reduced T once)
    fc_kernel<<<MTOT/64, 256>>>(qkfp, gt, fcH, fcL);

    // out = fc @ W2^T : all-bf16 one-shot, split everywhere
    out_bf16<<<dim3(16, 256), 256>>>(fcH, fcL, w2h, w2l, out);
}

// round 13
// speedup vs baseline: 1.1158x; 1.0645x over previous
#include <cuda_runtime.h>
#include <cuda_bf16.h>
#include <cstdint>

// Problem dims (fixed by the dataset)
#define BB 8
#define NSEQ 2048
#define DD 1024
#define DKK 64
#define MTOT (BB*NSEQ)   // 16384

// ---------------- scratch (static __device__ — no allocation) ----------------
__device__ float    g_QKFP[(long)MTOT*256];  // Q[0:64] K[64:128] F[128:192] P[192:256]
__device__ float    g_U2part[32*DKK*DD];     // split-K partials of U2
__device__ float    g_Tpart[32*BB*DKK*DKK];  // split-L partials of T
__device__ float    g_T[BB*DKK*DKK];         // reduced T
__device__ uint32_t g_Wh[256*512];           // Wext bf16-hi, packed k-pairs
__device__ uint32_t g_Wl[64*512];            // Wext bf16-lo, rows 128..191 (W1)
__device__ uint32_t g_W2h[1024*32];          // W2 bf16-hi packed
__device__ uint32_t g_W2l[1024*32];          // W2 bf16-lo packed

// ---------------------------------------------------------------------------
// helpers
// ---------------------------------------------------------------------------
__device__ __forceinline__ float tf32_rna(float x) {
    uint32_t r;
    asm("cvt.rna.tf32.f32 %0, %1;" : "=r"(r) : "f"(x));
    return __uint_as_float(r);
}
__device__ __forceinline__ uint32_t f2u(float f) { return __float_as_uint(f); }
__device__ __forceinline__ uint32_t b2u(__nv_bfloat162 v) {
    return *reinterpret_cast<uint32_t*>(&v);
}
__device__ __forceinline__ void cvt_hilo(float x, float y,
                                         __nv_bfloat162& h, __nv_bfloat162& l)
{
    h = __floats2bfloat162_rn(x, y);
    l = __floats2bfloat162_rn(x - __bfloat162float(h.x), y - __bfloat162float(h.y));
}

__device__ __forceinline__ void mma_tf32(float (&d)[4],
    uint32_t a0, uint32_t a1, uint32_t a2, uint32_t a3,
    uint32_t b0, uint32_t b1)
{
    asm volatile(
        "mma.sync.aligned.m16n8k8.row.col.f32.tf32.tf32.f32 "
        "{%0,%1,%2,%3},{%4,%5,%6,%7},{%8,%9},{%0,%1,%2,%3};"
        : "+f"(d[0]), "+f"(d[1]), "+f"(d[2]), "+f"(d[3])
        : "r"(a0), "r"(a1), "r"(a2), "r"(a3), "r"(b0), "r"(b1));
}

__device__ __forceinline__ void mma_bf16(float (&d)[4],
    const uint32_t (&a)[4], const uint32_t (&b)[2])
{
    asm volatile(
        "mma.sync.aligned.m16n8k16.row.col.f32.bf16.bf16.f32 "
        "{%0,%1,%2,%3},{%4,%5,%6,%7},{%8,%9},{%0,%1,%2,%3};"
        : "+f"(d[0]), "+f"(d[1]), "+f"(d[2]), "+f"(d[3])
        : "r"(a[0]), "r"(a[1]), "r"(a[2]), "r"(a[3]), "r"(b[0]), "r"(b[1]));
}

__device__ __forceinline__ void ldmx4(uint32_t (&r)[4], uint32_t addr) {
    asm volatile("ldmatrix.sync.aligned.m8n8.x4.shared.b16 {%0,%1,%2,%3}, [%4];"
        : "=r"(r[0]), "=r"(r[1]), "=r"(r[2]), "=r"(r[3]) : "r"(addr));
}
__device__ __forceinline__ void ldmx2(uint32_t (&r)[2], uint32_t addr) {
    asm volatile("ldmatrix.sync.aligned.m8n8.x2.shared.b16 {%0,%1}, [%2];"
        : "=r"(r[0]), "=r"(r[1]) : "r"(addr));
}

__device__ __forceinline__ void cp16(uint32_t smem_addr, const void* gptr) {
    asm volatile("cp.async.cg.shared.global [%0], [%1], 16;"
        :: "r"(smem_addr), "l"(gptr));
}
__device__ __forceinline__ void cp_commit() {
    asm volatile("cp.async.commit_group;" ::: "memory");
}
__device__ __forceinline__ void cp_wait0() {
    asm volatile("cp.async.wait_group 0;" ::: "memory");
}
__device__ __forceinline__ void cp_wait1() {
    asm volatile("cp.async.wait_group 1;" ::: "memory");
}

// ===========================================================================
// prep_w: builds bf16 weight planes directly from the inputs.
// Wh rows: 0..63 Wq, 64..127 Wk, 128..191 W1 (lo plane -> Wl), 192..255 U2
// (U2 summed inline from the 32 split-K partials). Also W2 -> W2h/W2l.
// ===========================================================================
__global__ void prep_w(const float* __restrict__ Wq, const float* __restrict__ Wk,
                       const float* __restrict__ W1, const float* __restrict__ u2p,
                       const float* __restrict__ W2,
                       uint32_t* __restrict__ Wh, uint32_t* __restrict__ Wl,
                       uint32_t* __restrict__ W2h, uint32_t* __restrict__ W2l)
{
    int i = blockIdx.x * 256 + threadIdx.x;
    if (i < 256*512) {
        int row = i >> 9, p = i & 511;
        float x, y;
        if (row < 128) {
            const float* W = (row < 64) ? Wq : Wk;
            int r = row & 63;
            x = W[r*DD + 2*p];  y = W[r*DD + 2*p + 1];
        } else if (row < 192) {
            int r = row - 128;
            x = W1[r*DD + 2*p];  y = W1[r*DD + 2*p + 1];
        } else {
            int r = row - 192;
            float sx = 0.f, sy = 0.f;
            for (int s = 0; s < 32; s++) {
                sx += u2p[(long)s*DKK*DD + r*DD + 2*p];
                sy += u2p[(long)s*DKK*DD + r*DD + 2*p + 1];
            }
            x = sx;  y = sy;
        }
        __nv_bfloat162 h, l;
        cvt_hilo(x, y, h, l);
        Wh[i] = b2u(h);
        if (row >= 128 && row < 192) Wl[(row - 128) * 512 + p] = b2u(l);
    } else {
        int j = i - 256*512;
        if (j < 1024*32) {
            __nv_bfloat162 h, l;
            cvt_hilo(W2[2*j], W2[2*j + 1], h, l);
            W2h[j] = b2u(h);
            W2l[j] = b2u(l);
        }
    }
}

// ===========================================================================
// qkfp_fused: C[M,256] = x[M,1024] * Wext[256,1024]^T, ONE pass over x.
// (R10 configuration — interleaved MMA ordering.)
// ===========================================================================
extern __shared__ uint32_t smem_dyn[];

__global__ void __launch_bounds__(256, 2)
qkfp_fused(const float* __restrict__ xg, const uint32_t* __restrict__ Wh,
           const uint32_t* __restrict__ Wl, float* __restrict__ Cg)
{
    constexpr int SP = 20;
    constexpr int OA_L = 1280;
    constexpr int OB_H = 2560;
    constexpr int OB_L = 7680;
    constexpr int STG  = 8960;
    constexpr uint32_t STGB = STG * 4;

    uint32_t* Ahs = smem_dyn;

    const int m0 = blockIdx.x * 64;
    const int tid = threadIdx.x, lane = tid & 31, wid = tid >> 5;
    const int wn = wid;

    const uint32_t sbase = (uint32_t)__cvta_generic_to_shared(smem_dyn);

    const int arowoff = ((lane >> 3) & 1) * 8 + (lane & 7);
    const int akoff   = (lane >> 4) * 4;
    uint32_t a_addr[4];
    #pragma unroll
    for (int mt = 0; mt < 4; mt++)
        a_addr[mt] = sbase + ((mt * 16 + arowoff) * SP + akoff) * 4;
    const uint32_t dAl = OA_L * 4;
    const int lb = lane & 15;
    uint32_t b_addr[4], bl_addr;
    #pragma unroll
    for (int j = 0; j < 4; j++)
        b_addr[j] = sbase + (OB_H + (wn * 8 + j * 64 + (lb & 7)) * SP
                             + ((lb >> 3) & 1) * 4) * 4;
    bl_addr = sbase + (OB_L + (wn * 8 + (lb & 7)) * SP + ((lb >> 3) & 1) * 4) * 4;

    const int ar = tid >> 3, afq = (tid & 7) * 4;
    const int aso = ar * SP + (afq >> 1);
    const int br = tid >> 2, bc = (tid & 3) * 4;

    float4 va[2];
    auto ldgA = [&](int k0) {
        #pragma unroll
        for (int e = 0; e < 2; e++)
            va[e] = *(const float4*)(xg + (long)(m0 + ar + e*32) * DD + k0 + afq);
    };
    auto cpB = [&](int k0, int s) {
        uint32_t d0 = sbase + (s * STG + OB_H + br * SP + bc) * 4;
        #pragma unroll
        for (int e = 0; e < 4; e++)
            cp16(d0 + e * 64 * SP * 4, &Wh[(br + e*64) * 512 + (k0 >> 1) + bc]);
        cp16(sbase + (s * STG + OB_L + br * SP + bc) * 4,
             &Wl[br * 512 + (k0 >> 1) + bc]);
        cp_commit();
    };
    auto stA = [&](int s) {
        #pragma unroll
        for (int e = 0; e < 2; e++) {
            float4 v = va[e];
            __nv_bfloat162 h0, l0, h1, l1;
            cvt_hilo(v.x, v.y, h0, l0);  cvt_hilo(v.z, v.w, h1, l1);
            int o = s * STG + aso + e * 32 * SP;
            Ahs[o]        = b2u(h0);  Ahs[o + 1]        = b2u(h1);
            Ahs[OA_L + o] = b2u(l0);  Ahs[OA_L + o + 1] = b2u(l1);
        }
    };

    float acc[4][4][4] = {};

    ldgA(0);
    cpB(0, 0);
    stA(0);
    cp_wait0();
    __syncthreads();

    int s = 0;
    for (int k0 = 0; k0 < DD; k0 += 32, s ^= 1) {
        const bool more = (k0 + 32) < DD;
        if (more) {
            ldgA(k0 + 32);
            cpB(k0 + 32, s ^ 1);
        }

        const uint32_t so = s * STGB;
        #pragma unroll
        for (int kp = 0; kp < 2; kp++) {
            const uint32_t kb = so + kp * 32;
            uint32_t bh[4][2], bl2[2];
            #pragma unroll
            for (int j = 0; j < 4; j++) ldmx2(bh[j], b_addr[j] + kb);
            ldmx2(bl2, bl_addr + kb);
            #pragma unroll
            for (int mt = 0; mt < 4; mt++) {
                uint32_t ah4[4], al4[4];
                ldmx4(ah4, a_addr[mt] + kb);
                #pragma unroll
                for (int j = 0; j < 4; j++)
                    mma_bf16(acc[mt][j], ah4, bh[j]);
                ldmx4(al4, a_addr[mt] + dAl + kb);
                mma_bf16(acc[mt][2], ah4, bl2);    // hi*lo (F)
                mma_bf16(acc[mt][2], al4, bh[2]);  // lo*hi (F)
            }
        }

        if (more) stA(s ^ 1);
        cp_wait0();
        __syncthreads();
    }

    const int r4 = lane >> 2, c4 = lane & 3;
    #pragma unroll
    for (int mt = 0; mt < 4; mt++)
        #pragma unroll
        for (int j = 0; j < 4; j++) {
            int row = m0 + mt * 16 + r4;
            int col = wn * 8 + j * 64 + 2 * c4;
            *(float2*)(Cg + (long)row * 256 + col) =
                make_float2(acc[mt][j][0], acc[mt][j][1]);
            *(float2*)(Cg + (long)(row + 8) * 256 + col) =
                make_float2(acc[mt][j][2], acc[mt][j][3]);
        }
}

// ===========================================================================
// fcout: fused fc + out.
// Block = one 64-row m-tile. Phase 1: fc = F + Q@T_b in fp32 (identical math
// to the old fc_kernel), converted to bf16 hi/lo planes in smem. Phase 2:
// loop 16 n-tiles of W2 (cp.async double-buffered), out-tile MMAs identical
// to the old out_bf16 (hh, hl, lh per kp), store out directly.
// Dynamic smem layout (uint32):
//   Qs [0,4352)  Ts [4352,8704)  Ah [8704,11008)  Al [11008,13312)
//   B stages: base 13312 + st*4608, plane Bh at +0, Bl at +2304 (SP=36)
// total 22528 u32 = 90112 B
// ===========================================================================
__global__ void __launch_bounds__(256, 2)
fcout(const float* __restrict__ qkfp, const float* __restrict__ T,
      const uint32_t* __restrict__ W2h, const uint32_t* __restrict__ W2l,
      float* __restrict__ out)
{
    constexpr int SP = 36;
    constexpr int O_TS = 4352;
    constexpr int O_AH = 8704;
    constexpr int O_AL = 11008;
    constexpr int O_B  = 13312;
    constexpr int BSTG = 4608;        // per-stage stride (Bh+Bl)
    constexpr int O_BL = 2304;        // Bl offset within stage

    float*    Qs  = (float*)smem_dyn;
    float*    Ts  = (float*)smem_dyn + O_TS;
    uint32_t* Ahp = smem_dyn + O_AH;
    uint32_t* Alp = smem_dyn + O_AL;

    const int r0 = blockIdx.x * 64;
    const int b  = r0 / NSEQ;
    const int tid = threadIdx.x, lane = tid & 31, wid = tid >> 5;
    const uint32_t sbase = (uint32_t)__cvta_generic_to_shared(smem_dyn);

    // ---------------- Phase 1: fc (identical to fc_kernel) ----------------
    #pragma unroll
    for (int e = 0; e < 4; e++) {
        int idx = tid + e * 256;
        int row = idx >> 4, fq = idx & 15;
        float4 q = *(const float4*)(qkfp + (long)(r0 + row) * 256 + fq * 4);
        *(float4*)&Qs[row * 68 + fq * 4] = q;
        float4 t = *(const float4*)(T + (long)b * 4096 + row * 64 + fq * 4);
        *(float4*)&Ts[row * 68 + fq * 4] = t;
    }
    __syncthreads();

    {
        const int row  = tid >> 2;
        const int col0 = (tid & 3) * 16;
        float acc[16];
        #pragma unroll
        for (int j = 0; j < 16; j += 4) {
            float4 f = *(const float4*)(qkfp + (long)(r0 + row) * 256 + 128 + col0 + j);
            acc[j] = f.x; acc[j+1] = f.y; acc[j+2] = f.z; acc[j+3] = f.w;
        }
        #pragma unroll 8
        for (int k = 0; k < 64; k++) {
            float q = Qs[row * 68 + k];
            #pragma unroll
            for (int j = 0; j < 16; j += 4) {
                float4 t = *(const float4*)&Ts[k * 68 + col0 + j];
                acc[j]   += q * t.x;  acc[j+1] += q * t.y;
                acc[j+2] += q * t.z;  acc[j+3] += q * t.w;
            }
        }
        const int ob = row * SP + (col0 >> 1);
        #pragma unroll
        for (int jj = 0; jj < 8; jj++) {
            __nv_bfloat162 h, l;
            cvt_hilo(acc[2*jj], acc[2*jj + 1], h, l);
            Ahp[ob + jj] = b2u(h);
            Alp[ob + jj] = b2u(l);
        }
    }

    // ---------------- Phase 2: out tiles (identical math to out_bf16) -----
    const int wm0 = (wid & 1) * 32, wn0 = (wid >> 1) * 16;
    const int arowoff = ((lane >> 3) & 1) * 8 + (lane & 7);
    const int akoff   = (lane >> 4) * 4;
    uint32_t a_addr[2];
    #pragma unroll
    for (int mt = 0; mt < 2; mt++)
        a_addr[mt] = sbase + (O_AH + (wm0 + mt * 16 + arowoff) * SP + akoff) * 4;
    const uint32_t dAl = (O_AL - O_AH) * 4;
    const int lb = lane & 15;
    uint32_t b_addr[2];
    #pragma unroll
    for (int nt = 0; nt < 2; nt++)
        b_addr[nt] = sbase + (O_B + (wn0 + nt * 8 + (lb & 7)) * SP
                              + ((lb >> 3) & 1) * 4) * 4;
    const uint32_t dBl = O_BL * 4;

    // W2 tile loader: 64 rows x 32 u32 per plane, 2 x 16B chunks per thread
    const int wr = tid >> 3, wc = (tid & 7) * 4;
    auto cpW = [&](int nt, int s) {
        uint32_t d0 = sbase + (O_B + s * BSTG + wr * SP + wc) * 4;
        cp16(d0,            &W2h[(long)(nt * 64 + wr) * 32 + wc]);
        cp16(d0 + dBl,      &W2l[(long)(nt * 64 + wr) * 32 + wc]);
        uint32_t d1 = sbase + (O_B + s * BSTG + (wr + 32) * SP + wc) * 4;
        cp16(d1,            &W2h[(long)(nt * 64 + wr + 32) * 32 + wc]);
        cp16(d1 + dBl,      &W2l[(long)(nt * 64 + wr + 32) * 32 + wc]);
        cp_commit();
    };

    cpW(0, 0);

    const int r4 = lane >> 2, c4 = lane & 3;
    int s = 0;
    for (int nt = 0; nt < 16; nt++, s ^= 1) {
        if (nt < 15) {
            cpW(nt + 1, s ^ 1);
            cp_wait1();          // stage s group done (one newer in flight)
        } else {
            cp_wait0();
        }
        __syncthreads();         // smem visibility across threads (also covers fc planes on nt==0)

        const uint32_t sB = s * BSTG * 4;
        float acc[2][2][4] = {};
        #pragma unroll
        for (int kp = 0; kp < 4; kp++) {
            const uint32_t kb = kp * 32;
            uint32_t ah[2][4], al[2][4], bh[2][2], bl[2][2];
            #pragma unroll
            for (int mt = 0; mt < 2; mt++) ldmx4(ah[mt], a_addr[mt] + kb);
            #pragma unroll
            for (int ns = 0; ns < 2; ns++) ldmx2(bh[ns], b_addr[ns] + sB + kb);
            #pragma unroll
            for (int mt = 0; mt < 2; mt++) ldmx4(al[mt], a_addr[mt] + dAl + kb);
            #pragma unroll
            for (int ns = 0; ns < 2; ns++) ldmx2(bl[ns], b_addr[ns] + sB + dBl + kb);
            #pragma unroll
            for (int mt = 0; mt < 2; mt++)
                #pragma unroll
                for (int ns = 0; ns < 2; ns++) {
                    mma_bf16(acc[mt][ns], ah[mt], bh[ns]);
                    mma_bf16(acc[mt][ns], ah[mt], bl[ns]);
                    mma_bf16(acc[mt][ns], al[mt], bh[ns]);
                }
        }

        #pragma unroll
        for (int mt = 0; mt < 2; mt++)
            #pragma unroll
            for (int ns = 0; ns < 2; ns++) {
                int row = r0 + wm0 + mt * 16 + r4;
                int col = nt * 64 + wn0 + ns * 8 + 2 * c4;
                *(float2*)(out + (long)row * 1024 + col) =
                    make_float2(acc[mt][ns][0], acc[mt][ns][1]);
                *(float2*)(out + (long)(row + 8) * 1024 + col) =
                    make_float2(acc[mt][ns][2], acc[mt][ns][3]);
            }
        __syncthreads();         // all reads of stage s done before next cpW overwrites it
    }
}

// ===========================================================================
// Tensor GEMM (tf32), ATB form: C[64,N] = A[L,64]^T * B[L,N] over rows L.
// ===========================================================================
__global__ void __launch_bounds__(256)
tgemm_atb(const float* __restrict__ Ag, int lda, long sAb,
          const float* __restrict__ Bg, int ldb, long sBb,
          float* __restrict__ Cg, long sCb, long sCsplit, int ldc,
          int Lchunk)
{
    constexpr int BK = 16, LDT = 64 + 4;
    __shared__ float As[BK][LDT];
    __shared__ float Bs[BK][LDT];

    const int b = blockIdx.z, sp = blockIdx.y;
    const long l0b = (long)sp * Lchunk;
    Ag += (long)b * sAb;  Bg += (long)b * sBb;
    Cg += (long)b * sCb + (long)sp * sCsplit;
    const int n0 = blockIdx.x * 64;
    const int tid = threadIdx.x, lane = tid & 31, wid = tid >> 5;
    const int wm0 = (wid & 1) * 32, wn0 = (wid >> 1) * 16;
    const int r4 = lane >> 2, c4 = lane & 3;
    const int lrow = tid >> 4, lc4 = (tid & 15) * 4;

    float acc[2][2][4] = {};
    float4 va, vb;

    auto ldg = [&](int l0) {
        va = *(const float4*)(Ag + (l0b + l0 + lrow) * lda + lc4);
        vb = *(const float4*)(Bg + (l0b + l0 + lrow) * ldb + n0 + lc4);
    };
    auto store = [&]() {
        As[lrow][lc4+0] = tf32_rna(va.x);  As[lrow][lc4+1] = tf32_rna(va.y);
        As[lrow][lc4+2] = tf32_rna(va.z);  As[lrow][lc4+3] = tf32_rna(va.w);
        Bs[lrow][lc4+0] = tf32_rna(vb.x);  Bs[lrow][lc4+1] = tf32_rna(vb.y);
        Bs[lrow][lc4+2] = tf32_rna(vb.z);  Bs[lrow][lc4+3] = tf32_rna(vb.w);
    };

    ldg(0);
    store();
    __syncthreads();

    for (int l0 = 0; l0 < Lchunk; l0 += BK) {
        const bool more = (l0 + BK) < Lchunk;
        if (more) ldg(l0 + BK);

        #pragma unroll
        for (int kk = 0; kk < BK; kk += 8) {
            uint32_t af[2][4], bf[2][2];
            #pragma unroll
            for (int mt = 0; mt < 2; mt++) {
                int row = wm0 + mt*16 + r4;
                af[mt][0] = f2u(As[kk + c4    ][row    ]);
                af[mt][1] = f2u(As[kk + c4    ][row + 8]);
                af[mt][2] = f2u(As[kk + c4 + 4][row    ]);
                af[mt][3] = f2u(As[kk + c4 + 4][row + 8]);
            }
            #pragma unroll
            for (int nt = 0; nt < 2; nt++) {
                int col = wn0 + nt*8 + r4;
                bf[nt][0] = f2u(Bs[kk + c4    ][col]);
                bf[nt][1] = f2u(Bs[kk + c4 + 4][col]);
            }
            #pragma unroll
            for (int mt = 0; mt < 2; mt++)
                #pragma unroll
                for (int nt = 0; nt < 2; nt++)
                    mma_tf32(acc[mt][nt], af[mt][0], af[mt][1], af[mt][2], af[mt][3],
                             bf[nt][0], bf[nt][1]);
        }
        __syncthreads();
        if (more) {
            store();
            __syncthreads();
        }
    }
    #pragma unroll
    for (int mt = 0; mt < 2; mt++)
        #pragma unroll
        for (int nt = 0; nt < 2; nt++) {
            int row = wm0 + mt*16 + r4;
            int col = n0 + wn0 + nt*8 + 2*c4;
            *(float2*)(Cg + (long)row * ldc + col) =
                make_float2(acc[mt][nt][0], acc[mt][nt][1]);
            *(float2*)(Cg + (long)(row + 8) * ldc + col) =
                make_float2(acc[mt][nt][2], acc[mt][nt][3]);
        }
}

// ===========================================================================
// SIMT fp32 NN GEMM (U2 only): C[M,N] = A[M,K]*B[K,N], split-K via z
// ===========================================================================
template<int BM,int BN,int BK,int TM,int TN>
__global__ void __launch_bounds__((BM/TM)*(BN/TN))
gemm_nn(const float* __restrict__ A, long sA, int lda,
        const float* __restrict__ B, long sB, int ldb,
        float* __restrict__ C, long sC, int ldc,
        int K)
{
    constexpr int THREADS = (BM/TM)*(BN/TN);
    __shared__ float As[BK][BM];
    __shared__ float Bs[BK][BN];

    const int bz = blockIdx.z;
    A += bz * sA;  B += bz * sB;  C += bz * sC;

    const int m0 = blockIdx.y * BM;
    const int n0 = blockIdx.x * BN;
    const int tid = threadIdx.x;
    const int tx = tid % (BN/TN);
    const int ty = tid / (BN/TN);

    float acc[TM][TN];
    #pragma unroll
    for (int i = 0; i < TM; i++)
        #pragma unroll
        for (int j = 0; j < TN; j++) acc[i][j] = 0.f;

    for (int k0 = 0; k0 < K; k0 += BK) {
        #pragma unroll
        for (int e = 0; e < (BM*BK/4)/THREADS; e++) {
            int idx = tid + e*THREADS;
            int row = idx / (BK/4), cv = idx % (BK/4);
            float4 v = *(const float4*)(A + (long)(m0+row)*lda + k0 + cv*4);
            As[cv*4+0][row] = v.x;  As[cv*4+1][row] = v.y;
            As[cv*4+2][row] = v.z;  As[cv*4+3][row] = v.w;
        }
        #pragma unroll
        for (int e = 0; e < (BK*BN/4)/THREADS; e++) {
            int idx = tid + e*THREADS;
            int row = idx / (BN/4), cv = idx % (BN/4);
            *(float4*)&Bs[row][cv*4] =
                *(const float4*)(B + (long)(k0+row)*ldb + n0 + cv*4);
        }
        __syncthreads();
        #pragma unroll
        for (int k = 0; k < BK; k++) {
            float a[TM], b[TN];
            #pragma unroll
            for (int i = 0; i < TM; i += 4) *(float4*)(a+i) = *(const float4*)&As[k][ty*TM+i];
            #pragma unroll
            for (int j = 0; j < TN; j += 4) *(float4*)(b+j) = *(const float4*)&Bs[k][tx*TN+j];
            #pragma unroll
            for (int i = 0; i < TM; i++)
                #pragma unroll
                for (int j = 0; j < TN; j++) acc[i][j] += a[i]*b[j];
        }
        __syncthreads();
    }
    #pragma unroll
    for (int i = 0; i < TM; i++) {
        int row = m0 + ty*TM + i;
        #pragma unroll
        for (int j = 0; j < TN; j += 4) {
            float4 v;
            v.x = acc[i][j];   v.y = acc[i][j+1];
            v.z = acc[i][j+2]; v.w = acc[i][j+3];
            *(float4*)(C + (long)row*ldc + n0 + tx*TN + j) = v;
        }
    }
}

// Sum S split partials
template<int S>
__global__ void reduceN(const float* __restrict__ p, float* __restrict__ o, int n)
{
    int i = blockIdx.x * 256 + threadIdx.x;
    if (i < n) {
        float s = 0.f;
        #pragma unroll
        for (int j = 0; j < S; j++) s += p[i + (long)j * n];
        o[i] = s;
    }
}

// ============================================================================
extern "C" void kernel_launch(void* const* d_in, const int* in_sizes, int n_in,
                              void* d_out, int out_size)
{
    const float* x  = (const float*)d_in[0];   // [8,2048,1024]
    const float* Wq = (const float*)d_in[1];   // [64,1024]
    const float* Wk = (const float*)d_in[2];   // [64,1024]
    const float* Wv = (const float*)d_in[3];   // [1024,1024]
    const float* W1 = (const float*)d_in[4];   // [64,1024]
    const float* W2 = (const float*)d_in[5];   // [1024,64]
    float* out = (float*)d_out;                // [8,2048,1024]

    float *qkfp, *u2p, *tpart, *gt;
    uint32_t *wh, *wl, *w2h, *w2l;
    cudaGetSymbolAddress((void**)&qkfp,  g_QKFP);
    cudaGetSymbolAddress((void**)&u2p,   g_U2part);
    cudaGetSymbolAddress((void**)&tpart, g_Tpart);
    cudaGetSymbolAddress((void**)&gt,    g_T);
    cudaGetSymbolAddress((void**)&wh,    g_Wh);
    cudaGetSymbolAddress((void**)&wl,    g_Wl);
    cudaGetSymbolAddress((void**)&w2h,   g_W2h);
    cudaGetSymbolAddress((void**)&w2l,   g_W2l);

    static_assert(2 * 8960 * 4 == 71680, "qkfp stage size");
    cudaFuncSetAttribute(qkfp_fused,
                         cudaFuncAttributeMaxDynamicSharedMemorySize, 71680);
    static_assert(22528 * 4 == 90112, "fcout smem size");
    cudaFuncSetAttribute(fcout,
                         cudaFuncAttributeMaxDynamicSharedMemorySize, 90112);

    // U2 = W1 @ Wv : [64,1024], 32-way split-K partials
    gemm_nn<64,64,16,4,4><<<dim3(16,1,32), 256>>>(
        W1, 32, DD,  Wv, (long)32*DD, DD,  u2p, (long)DKK*DD, DD,  32);

    // Build all bf16 weight planes
    prep_w<<<(256*512 + 1024*32 + 255)/256, 256>>>(
        Wq, Wk, W1, u2p, W2, wh, wl, w2h, w2l);

    // QKFP = x @ Wext^T : one pass over x, F columns split, 2 blocks/SM
    qkfp_fused<<<256, 256, 71680>>>(x, wh, wl, qkfp);

    // T_b partials = K_b^T P_b : 32-way L-split + reduce (R10 config)
    tgemm_atb<<<dim3(1, 32, 8), 256>>>(
        qkfp + 64,  256, (long)NSEQ*256,
        qkfp + 192, 256, (long)NSEQ*256,
        tpart, (long)DKK*DKK, (long)BB*DKK*DKK, DKK,
        NSEQ/32);
    reduceN<32><<<(BB*DKK*DKK + 255)/256, 256>>>(tpart, gt, BB*DKK*DKK);

    // fused fc + out
    fcout<<<256, 256, 90112>>>(qkfp, gt, w2h, w2l, out);
}